// round 6
// baseline (speedup 1.0000x reference)
#include <cuda_runtime.h>
#include <cuda_bf16.h>
#include <math.h>

// ---------------- problem constants ----------------
#define TT     1024      // tokens
#define HH     2048      // hidden
#define EE     32        // routed experts
#define TOPK   6
#define NGROUP 8
#define TOPKG  3
#define EPG    (EE/NGROUP)   // 4 experts per group
#define IMOE   768
#define ISH    1536          // 2 * IMOE
#define CAPE   768           // per-expert capacity
#define RSCALE 16.0f

// ---------------- scratch (static device globals; no allocation) ----------------
__device__ float g_logits[(size_t)TT*EE];            // router logits [1024,32]
__device__ float g_gu   [(size_t)TT*TOPK * 2*IMOE];  // routed gate_up outputs  [6144,1536]
__device__ float g_h    [(size_t)TT*TOPK * IMOE];    // routed silu*up          [6144, 768]
__device__ float g_y    [(size_t)TT*TOPK * HH];      // routed expert outputs   [6144,2048]
__device__ float g_gu_sh[(size_t)TT * 2*ISH];        // shared gate_up          [1024,3072]
__device__ float g_h_sh [(size_t)TT * ISH];          // shared silu*up          [1024,1536]
__device__ float g_wcomb[TT*TOPK];                   // combine weights (0 if dropped)
__device__ int   g_slot_tok [EE*CAPE];               // token index per expert slot
__device__ int   g_slot_flat[EE*CAPE];               // flat (t*K+k) per expert slot
__device__ int   g_cnt[EE];                          // per-expert assignment count

// ---------------- init: zero per-expert counters ----------------
__global__ void init_kernel() {
    if (threadIdx.x < EE) g_cnt[threadIdx.x] = 0;
}

// ---------------- router logits: one thread per (t,e), SEQUENTIAL ascending-k fp32 fma ----
// Bit-replicates the per-output single-accumulator ascending-k chain used by both
// cutlass SIMT SGEMM (GPU) and Eigen gebp (CPU) — the two plausible reference backends.
__global__ void logits_kernel(const float* __restrict__ x,
                              const float* __restrict__ gate_w) {
    __shared__ float sx[4][HH];               // 4 tokens staged, 32KB
    const int t0 = blockIdx.x * 4;
    const int tid = threadIdx.x;              // 128 threads: 4 tokens x 32 experts
    for (int i = tid; i < 4*HH; i += 128)
        sx[i >> 11][i & (HH-1)] = x[(size_t)(t0 + (i >> 11)) * HH + (i & (HH-1))];
    __syncthreads();

    const int tl = tid & 3;
    const int e  = tid >> 2;
    const float* gw = gate_w + (size_t)e * HH;
    float acc = 0.f;
    #pragma unroll 8
    for (int k = 0; k < HH; ++k)
        acc = fmaf(sx[tl][k], gw[k], acc);    // single chain, ascending k
    g_logits[(size_t)(t0 + tl) * EE + e] = acc;
}

// ---------------- selection: fp32 softmax (jax form) + group-limited top-k + dispatch ----
__global__ void select_kernel() {
    const int t = blockIdx.x * blockDim.x + threadIdx.x;
    if (t >= TT) return;
    const float* l = g_logits + (size_t)t * EE;

    // softmax exactly as jax.nn.softmax: max -> exp -> ascending sum -> division
    float mx = l[0];
    for (int e = 1; e < EE; ++e) mx = fmaxf(mx, l[e]);
    float ex[EE]; float sum = 0.f;
    for (int e = 0; e < EE; ++e) { ex[e] = expf(l[e] - mx); sum += ex[e]; }
    float sc[EE];
    for (int e = 0; e < EE; ++e) sc[e] = ex[e] / sum;

    // group scores = max within group of 4
    float gs[NGROUP];
    for (int g = 0; g < NGROUP; ++g) {
        float m = sc[g * EPG];
        for (int j = 1; j < EPG; ++j) m = fmaxf(m, sc[g * EPG + j]);
        gs[g] = m;
    }
    // top-3 groups (strict > keeps lowest index on ties, matching jax.lax.top_k)
    bool gsel[NGROUP];
    for (int g = 0; g < NGROUP; ++g) gsel[g] = false;
    for (int r = 0; r < TOPKG; ++r) {
        int best = -1; float bv = -1e30f;
        for (int g = 0; g < NGROUP; ++g)
            if (!gsel[g] && gs[g] > bv) { bv = gs[g]; best = g; }
        gsel[best] = true;
    }
    // masked scores, then top-6
    float ms[EE];
    for (int e = 0; e < EE; ++e) ms[e] = gsel[e / EPG] ? sc[e] : 0.f;
    for (int k = 0; k < TOPK; ++k) {
        int best = 0; float bv = -1.f;
        for (int e = 0; e < EE; ++e)
            if (ms[e] > bv) { bv = ms[e]; best = e; }
        ms[best] = -1.f;
        const int flat = t * TOPK + k;
        const int pos = atomicAdd(&g_cnt[best], 1);
        if (pos < CAPE) {
            g_slot_tok [best * CAPE + pos] = t;
            g_slot_flat[best * CAPE + pos] = flat;
            g_wcomb[flat] = bv;
        } else {
            g_wcomb[flat] = 0.f;   // dropped (never happens at 4x capacity)
        }
    }
}

// ---------------- generic NT SGEMM body: C[m,n] = sum_k A[m,k]*B[n,k] ----------------
// EXACT fp32 operands, fp32 fma accumulate.
// 64x64 tile, BK=16, 256 threads, 4x4 microtile. Optional row gather (A) / scatter (C).
__device__ __forceinline__ void gemm_nt_body(
    const float* __restrict__ A, int lda,
    const float* __restrict__ B,            // ldb == Klen (row-major [N,Klen])
    float* __restrict__ C, int ldc,
    const int* __restrict__ arow,           // nullable: A row = arow[m]
    const int* __restrict__ crow,           // nullable: C row = crow[m]
    int M, int Klen)
{
    constexpr int BM = 64, BN = 64, BK = 16;
    const int m0 = blockIdx.y * BM;
    if (m0 >= M) return;
    const int n0 = blockIdx.x * BN;

    __shared__ float As[BK][BM + 4];
    __shared__ float Bs[BK][BN + 4];

    const int tid = threadIdx.x;
    const int tx = tid & 15, ty = tid >> 4;
    const int lr = tid >> 2;          // 0..63
    const int lk = (tid & 3) * 4;     // 0,4,8,12

    const int am = m0 + lr;
    const bool am_ok = am < M;
    long long arowidx = 0;
    if (am_ok) arowidx = arow ? arow[am] : am;
    const float* Aptr = A + arowidx * (long long)lda + lk;
    const float* Bptr = B + (long long)(n0 + lr) * Klen + lk;

    float acc[4][4] = {};

    for (int k0 = 0; k0 < Klen; k0 += BK) {
        float4 av = am_ok ? *(const float4*)(Aptr + k0) : make_float4(0.f,0.f,0.f,0.f);
        float4 bv = *(const float4*)(Bptr + k0);
        __syncthreads();
        As[lk+0][lr]=av.x; As[lk+1][lr]=av.y; As[lk+2][lr]=av.z; As[lk+3][lr]=av.w;
        Bs[lk+0][lr]=bv.x; Bs[lk+1][lr]=bv.y; Bs[lk+2][lr]=bv.z; Bs[lk+3][lr]=bv.w;
        __syncthreads();
        #pragma unroll
        for (int k = 0; k < BK; ++k) {
            float a[4], b[4];
            #pragma unroll
            for (int i = 0; i < 4; ++i) a[i] = As[k][ty*4+i];
            #pragma unroll
            for (int j = 0; j < 4; ++j) b[j] = Bs[k][tx*4+j];
            #pragma unroll
            for (int i = 0; i < 4; ++i)
                #pragma unroll
                for (int j = 0; j < 4; ++j)
                    acc[i][j] = fmaf(a[i], b[j], acc[i][j]);
        }
    }

    #pragma unroll
    for (int i = 0; i < 4; ++i) {
        const int m = m0 + ty*4 + i;
        if (m < M) {
            const long long crr = crow ? crow[m] : m;
            float4 v = make_float4(acc[i][0], acc[i][1], acc[i][2], acc[i][3]);
            *(float4*)(C + crr * (long long)ldc + n0 + tx*4) = v;
        }
    }
}

// ---- GEMM wrappers binding the right buffers (blockIdx.z = expert) ----
__global__ void gemm_routed1(const float* __restrict__ x, const float* __restrict__ w13) {
    const int e = blockIdx.z;
    const int M = min(g_cnt[e], CAPE);
    gemm_nt_body(x, HH,
                 w13 + (long long)e * (2*IMOE) * HH,
                 g_gu, 2*IMOE,
                 g_slot_tok + e*CAPE, g_slot_flat + e*CAPE,
                 M, HH);
}
__global__ void gemm_routed2(const float* __restrict__ w2) {
    const int e = blockIdx.z;
    const int M = min(g_cnt[e], CAPE);
    gemm_nt_body(g_h, IMOE,
                 w2 + (long long)e * HH * IMOE,
                 g_y, HH,
                 g_slot_flat + e*CAPE, g_slot_flat + e*CAPE,
                 M, IMOE);
}
__global__ void gemm_shared1(const float* __restrict__ x, const float* __restrict__ sgu) {
    gemm_nt_body(x, HH, sgu, g_gu_sh, 2*ISH, nullptr, nullptr, TT, HH);
}
__global__ void gemm_shared2(const float* __restrict__ sdn, float* __restrict__ out) {
    gemm_nt_body(g_h_sh, ISH, sdn, out, HH, nullptr, nullptr, TT, ISH);
}

// ---------------- SwiGLU elementwise (exact fp32, accurate expf) ----------------
__global__ void swiglu_routed() {
    const int slot = blockIdx.x;                 // e*CAPE + pos
    const int e = slot / CAPE, pos = slot % CAPE;
    if (pos >= g_cnt[e]) return;
    const int flat = g_slot_flat[slot];
    const float* gu = g_gu + (long long)flat * (2*IMOE);
    float* h = g_h + (long long)flat * IMOE;
    for (int i = threadIdx.x; i < IMOE; i += blockDim.x) {
        float g = gu[i], u = gu[i + IMOE];
        h[i] = u * g / (1.f + expf(-g));
    }
}
__global__ void swiglu_shared() {
    const int t = blockIdx.x;
    const float* gu = g_gu_sh + (long long)t * (2*ISH);
    float* h = g_h_sh + (long long)t * ISH;
    for (int i = threadIdx.x; i < ISH; i += blockDim.x) {
        float g = gu[i], u = gu[i + ISH];
        h[i] = u * g / (1.f + expf(-g));
    }
}

// ---------------- combine: out += SCALE * sum_k w_k * y_k (exact fp32) ----------------
__global__ void combine_kernel(float* __restrict__ out) {
    const int t = blockIdx.x;
    const int base = t * TOPK;
    float w[TOPK];
    #pragma unroll
    for (int k = 0; k < TOPK; ++k) w[k] = g_wcomb[base + k];
    float* orow = out + (long long)t * HH;
    for (int h = threadIdx.x; h < HH; h += blockDim.x) {
        float r = 0.f;
        #pragma unroll
        for (int k = 0; k < TOPK; ++k)
            r += w[k] * g_y[(long long)(base + k) * HH + h];
        orow[h] += RSCALE * r;
    }
}

// ---------------- launch ----------------
extern "C" void kernel_launch(void* const* d_in, const int* in_sizes, int n_in,
                              void* d_out, int out_size) {
    const float* x     = (const float*)d_in[0];   // [T,H]
    const float* gatew = (const float*)d_in[1];   // [E,H]
    const float* w13   = (const float*)d_in[2];   // [E,2I,H]
    const float* w2    = (const float*)d_in[3];   // [E,H,I]
    const float* sgu   = (const float*)d_in[4];   // [2*ISH,H]
    const float* sdn   = (const float*)d_in[5];   // [H,ISH]
    float* out = (float*)d_out;                   // [T,H]

    init_kernel<<<1, 32>>>();
    logits_kernel<<<TT/4, 128>>>(x, gatew);
    select_kernel<<<4, 256>>>();

    // routed path
    {
        dim3 g(2*IMOE/64, CAPE/64, EE);           // (24,12,32)
        gemm_routed1<<<g, 256>>>(x, w13);
    }
    swiglu_routed<<<EE*CAPE, 256>>>();
    {
        dim3 g(HH/64, CAPE/64, EE);               // (32,12,32)
        gemm_routed2<<<g, 256>>>(w2);
    }

    // shared-expert path (writes d_out fully)
    {
        dim3 g(2*ISH/64, TT/64, 1);               // (48,16)
        gemm_shared1<<<g, 256>>>(x, sgu);
    }
    swiglu_shared<<<TT, 256>>>();
    {
        dim3 g(HH/64, TT/64, 1);                  // (32,16)
        gemm_shared2<<<g, 256>>>(sdn, out);
    }

    // combine routed into out
    combine_kernel<<<TT, 256>>>(out);
}

// round 7
// speedup vs baseline: 2.6669x; 2.6669x over previous
#include <cuda_runtime.h>
#include <cuda_bf16.h>
#include <math.h>
#include <stdint.h>

// ---------------- problem constants ----------------
#define TT     1024      // tokens
#define HH     2048      // hidden
#define EE     32        // routed experts
#define TOPK   6
#define NGROUP 8
#define TOPKG  3
#define EPG    (EE/NGROUP)   // 4 experts per group
#define IMOE   768
#define ISH    1536          // 2 * IMOE
#define CAPE   768           // per-expert capacity
#define RSCALE 16.0f

// ---------------- scratch (static device globals; no allocation) ----------------
__device__ float g_logits[(size_t)TT*EE];            // router logits [1024,32]
__device__ float g_gu   [(size_t)TT*TOPK * 2*IMOE];  // routed gate_up outputs  [6144,1536]
__device__ float g_h    [(size_t)TT*TOPK * IMOE];    // routed silu*up          [6144, 768]
__device__ float g_y    [(size_t)TT*TOPK * HH];      // routed expert outputs   [6144,2048]
__device__ float g_gu_sh[(size_t)TT * 2*ISH];        // shared gate_up          [1024,3072]
__device__ float g_h_sh [(size_t)TT * ISH];          // shared silu*up          [1024,1536]
__device__ float g_wcomb[TT*TOPK];                   // combine weights (0 if dropped)
__device__ int   g_slot_tok [EE*CAPE];               // token index per expert slot
__device__ int   g_slot_flat[EE*CAPE];               // flat (t*K+k) per expert slot
__device__ int   g_cnt[EE];                          // per-expert assignment count

// ---------------- init ----------------
__global__ void init_kernel() {
    if (threadIdx.x < EE) g_cnt[threadIdx.x] = 0;
}

// ---------------- router logits: one thread per (t,e), SEQUENTIAL ascending-k fp32 fma ----
// Bit-replicates the reference's per-output single-accumulator ascending-k chain.
// DO NOT TOUCH: this exact ordering is what makes routing decisions match.
__global__ void logits_kernel(const float* __restrict__ x,
                              const float* __restrict__ gate_w) {
    __shared__ float sx[4][HH];               // 4 tokens staged, 32KB
    const int t0 = blockIdx.x * 4;
    const int tid = threadIdx.x;              // 128 threads: 4 tokens x 32 experts
    for (int i = tid; i < 4*HH; i += 128)
        sx[i >> 11][i & (HH-1)] = x[(size_t)(t0 + (i >> 11)) * HH + (i & (HH-1))];
    __syncthreads();

    const int tl = tid & 3;
    const int e  = tid >> 2;
    const float* gw = gate_w + (size_t)e * HH;
    float acc = 0.f;
    #pragma unroll 8
    for (int k = 0; k < HH; ++k)
        acc = fmaf(sx[tl][k], gw[k], acc);    // single chain, ascending k
    g_logits[(size_t)(t0 + tl) * EE + e] = acc;
}

// ---------------- selection: fp32 softmax (jax form) + group-limited top-k + dispatch ----
__global__ void select_kernel() {
    const int t = blockIdx.x * blockDim.x + threadIdx.x;
    if (t >= TT) return;
    const float* l = g_logits + (size_t)t * EE;

    float mx = l[0];
    for (int e = 1; e < EE; ++e) mx = fmaxf(mx, l[e]);
    float ex[EE]; float sum = 0.f;
    for (int e = 0; e < EE; ++e) { ex[e] = expf(l[e] - mx); sum += ex[e]; }
    float sc[EE];
    for (int e = 0; e < EE; ++e) sc[e] = ex[e] / sum;

    float gs[NGROUP];
    for (int g = 0; g < NGROUP; ++g) {
        float m = sc[g * EPG];
        for (int j = 1; j < EPG; ++j) m = fmaxf(m, sc[g * EPG + j]);
        gs[g] = m;
    }
    bool gsel[NGROUP];
    for (int g = 0; g < NGROUP; ++g) gsel[g] = false;
    for (int r = 0; r < TOPKG; ++r) {
        int best = -1; float bv = -1e30f;
        for (int g = 0; g < NGROUP; ++g)
            if (!gsel[g] && gs[g] > bv) { bv = gs[g]; best = g; }
        gsel[best] = true;
    }
    float ms[EE];
    for (int e = 0; e < EE; ++e) ms[e] = gsel[e / EPG] ? sc[e] : 0.f;
    for (int k = 0; k < TOPK; ++k) {
        int best = 0; float bv = -1.f;
        for (int e = 0; e < EE; ++e)
            if (ms[e] > bv) { bv = ms[e]; best = e; }
        ms[best] = -1.f;
        const int flat = t * TOPK + k;
        const int pos = atomicAdd(&g_cnt[best], 1);
        if (pos < CAPE) {
            g_slot_tok [best * CAPE + pos] = t;
            g_slot_flat[best * CAPE + pos] = flat;
            g_wcomb[flat] = bv;
        } else {
            g_wcomb[flat] = 0.f;
        }
    }
}

// ================= TF32 tensor-core NT GEMM =================
// C[m,n] = sum_k A[m,k]*B[n,k]; operands cvt.rna.tf32 (cublas semantics), fp32 acc.
// 128x128x32 block tile, 256 threads = 2x4 warps, warp tile 64x32, mma.m16n8k8.
#define BM 128
#define BN 128
#define BKK 32

__device__ __forceinline__ uint32_t tf32b(float x) {
    uint32_t u;
    asm("cvt.rna.tf32.f32 %0, %1;" : "=r"(u) : "f"(x));
    return u;
}

__device__ __forceinline__ void mma_tf32(float c[4], const uint32_t a[4], const uint32_t b[2]) {
    asm volatile(
        "mma.sync.aligned.m16n8k8.row.col.f32.tf32.tf32.f32 "
        "{%0,%1,%2,%3}, {%4,%5,%6,%7}, {%8,%9}, {%0,%1,%2,%3};\n"
        : "+f"(c[0]), "+f"(c[1]), "+f"(c[2]), "+f"(c[3])
        : "r"(a[0]), "r"(a[1]), "r"(a[2]), "r"(a[3]), "r"(b[0]), "r"(b[1]));
}

__device__ __forceinline__ void gemm_tc_body(
    const float* __restrict__ A, int lda,
    const float* __restrict__ B,            // row-major [N, Klen]
    float* __restrict__ C, int ldc,
    const int* __restrict__ arow,           // nullable: A row = arow[m]
    const int* __restrict__ crow,           // nullable: C row = crow[m]
    int M, int Klen)
{
    const int m0 = blockIdx.y * BM;
    if (m0 >= M) return;
    const int n0 = blockIdx.x * BN;

    __shared__ uint32_t As[BM][BKK + 4];
    __shared__ uint32_t Bs[BN][BKK + 4];

    const int tid  = threadIdx.x;
    const int warp = tid >> 5, lane = tid & 31;
    const int wm = (warp & 1) * 64;           // warp m-offset within block
    const int wn = (warp >> 1) * 32;          // warp n-offset within block
    const int gid = lane >> 2, tig = lane & 3;

    // global-load mapping: each thread loads float4; 32 rows per pass, 4 passes
    const int lrow = tid >> 3;
    const int lcol = (tid & 7) * 4;

    // resolve gathered A rows once
    long long arows[4]; bool aok[4];
    #pragma unroll
    for (int p = 0; p < 4; ++p) {
        const int m = m0 + lrow + p * 32;
        aok[p] = m < M;
        arows[p] = aok[p] ? (arow ? arow[m] : m) : 0;
    }

    float acc[4][4][4];
    #pragma unroll
    for (int i = 0; i < 4; ++i)
        #pragma unroll
        for (int j = 0; j < 4; ++j)
            #pragma unroll
            for (int r = 0; r < 4; ++r) acc[i][j][r] = 0.f;

    for (int k0 = 0; k0 < Klen; k0 += BKK) {
        __syncthreads();
        #pragma unroll
        for (int p = 0; p < 4; ++p) {
            float4 av = aok[p] ? *(const float4*)(A + arows[p] * (long long)lda + k0 + lcol)
                               : make_float4(0.f, 0.f, 0.f, 0.f);
            uint32_t* ad = &As[lrow + p * 32][lcol];
            ad[0] = tf32b(av.x); ad[1] = tf32b(av.y); ad[2] = tf32b(av.z); ad[3] = tf32b(av.w);
            float4 bv = *(const float4*)(B + (long long)(n0 + lrow + p * 32) * Klen + k0 + lcol);
            uint32_t* bd = &Bs[lrow + p * 32][lcol];
            bd[0] = tf32b(bv.x); bd[1] = tf32b(bv.y); bd[2] = tf32b(bv.z); bd[3] = tf32b(bv.w);
        }
        __syncthreads();

        #pragma unroll
        for (int kk = 0; kk < BKK; kk += 8) {
            uint32_t af[4][4], bf[4][2];
            #pragma unroll
            for (int mt = 0; mt < 4; ++mt) {
                const int r = wm + mt * 16 + gid;
                af[mt][0] = As[r    ][kk + tig];
                af[mt][1] = As[r + 8][kk + tig];
                af[mt][2] = As[r    ][kk + tig + 4];
                af[mt][3] = As[r + 8][kk + tig + 4];
            }
            #pragma unroll
            for (int nt = 0; nt < 4; ++nt) {
                const int r = wn + nt * 8 + gid;
                bf[nt][0] = Bs[r][kk + tig];
                bf[nt][1] = Bs[r][kk + tig + 4];
            }
            #pragma unroll
            for (int mt = 0; mt < 4; ++mt)
                #pragma unroll
                for (int nt = 0; nt < 4; ++nt)
                    mma_tf32(acc[mt][nt], af[mt], bf[nt]);
        }
    }

    // epilogue: c0,c1 at (gid, 2*tig), c2,c3 at (gid+8, 2*tig)
    #pragma unroll
    for (int mt = 0; mt < 4; ++mt) {
        const int ma = m0 + wm + mt * 16 + gid;
        const int mb = ma + 8;
        #pragma unroll
        for (int nt = 0; nt < 4; ++nt) {
            const int col = n0 + wn + nt * 8 + 2 * tig;
            if (ma < M) {
                const long long r = crow ? crow[ma] : ma;
                *(float2*)(C + r * (long long)ldc + col) = make_float2(acc[mt][nt][0], acc[mt][nt][1]);
            }
            if (mb < M) {
                const long long r = crow ? crow[mb] : mb;
                *(float2*)(C + r * (long long)ldc + col) = make_float2(acc[mt][nt][2], acc[mt][nt][3]);
            }
        }
    }
}

// ---- GEMM wrappers (blockIdx.z = expert where applicable) ----
__global__ void __launch_bounds__(256, 2) gemm_routed1(const float* __restrict__ x, const float* __restrict__ w13) {
    const int e = blockIdx.z;
    const int M = min(g_cnt[e], CAPE);
    gemm_tc_body(x, HH,
                 w13 + (long long)e * (2*IMOE) * HH,
                 g_gu, 2*IMOE,
                 g_slot_tok + e*CAPE, g_slot_flat + e*CAPE,
                 M, HH);
}
__global__ void __launch_bounds__(256, 2) gemm_routed2(const float* __restrict__ w2) {
    const int e = blockIdx.z;
    const int M = min(g_cnt[e], CAPE);
    gemm_tc_body(g_h, IMOE,
                 w2 + (long long)e * HH * IMOE,
                 g_y, HH,
                 g_slot_flat + e*CAPE, g_slot_flat + e*CAPE,
                 M, IMOE);
}
__global__ void __launch_bounds__(256, 2) gemm_shared1(const float* __restrict__ x, const float* __restrict__ sgu) {
    gemm_tc_body(x, HH, sgu, g_gu_sh, 2*ISH, nullptr, nullptr, TT, HH);
}
__global__ void __launch_bounds__(256, 2) gemm_shared2(const float* __restrict__ sdn, float* __restrict__ out) {
    gemm_tc_body(g_h_sh, ISH, sdn, out, HH, nullptr, nullptr, TT, ISH);
}

// ---------------- SwiGLU elementwise (exact fp32) ----------------
__global__ void swiglu_routed() {
    const int slot = blockIdx.x;                 // e*CAPE + pos
    const int e = slot / CAPE, pos = slot % CAPE;
    if (pos >= g_cnt[e]) return;
    const int flat = g_slot_flat[slot];
    const float* gu = g_gu + (long long)flat * (2*IMOE);
    float* h = g_h + (long long)flat * IMOE;
    for (int i = threadIdx.x; i < IMOE; i += blockDim.x) {
        float g = gu[i], u = gu[i + IMOE];
        h[i] = u * g / (1.f + expf(-g));
    }
}
__global__ void swiglu_shared() {
    const int t = blockIdx.x;
    const float* gu = g_gu_sh + (long long)t * (2*ISH);
    float* h = g_h_sh + (long long)t * ISH;
    for (int i = threadIdx.x; i < ISH; i += blockDim.x) {
        float g = gu[i], u = gu[i + ISH];
        h[i] = u * g / (1.f + expf(-g));
    }
}

// ---------------- combine: out += SCALE * sum_k w_k * y_k ----------------
__global__ void combine_kernel(float* __restrict__ out) {
    const int t = blockIdx.x;
    const int base = t * TOPK;
    float w[TOPK];
    #pragma unroll
    for (int k = 0; k < TOPK; ++k) w[k] = g_wcomb[base + k];
    float* orow = out + (long long)t * HH;
    for (int h = threadIdx.x; h < HH; h += blockDim.x) {
        float r = 0.f;
        #pragma unroll
        for (int k = 0; k < TOPK; ++k)
            r += w[k] * g_y[(long long)(base + k) * HH + h];
        orow[h] += RSCALE * r;
    }
}

// ---------------- launch ----------------
extern "C" void kernel_launch(void* const* d_in, const int* in_sizes, int n_in,
                              void* d_out, int out_size) {
    const float* x     = (const float*)d_in[0];   // [T,H]
    const float* gatew = (const float*)d_in[1];   // [E,H]
    const float* w13   = (const float*)d_in[2];   // [E,2I,H]
    const float* w2    = (const float*)d_in[3];   // [E,H,I]
    const float* sgu   = (const float*)d_in[4];   // [2*ISH,H]
    const float* sdn   = (const float*)d_in[5];   // [H,ISH]
    float* out = (float*)d_out;                   // [T,H]

    init_kernel<<<1, 32>>>();
    logits_kernel<<<TT/4, 128>>>(x, gatew);
    select_kernel<<<4, 256>>>();

    // routed path
    {
        dim3 g((2*IMOE)/BN, CAPE/BM, EE);         // (12,6,32)
        gemm_routed1<<<g, 256>>>(x, w13);
    }
    swiglu_routed<<<EE*CAPE, 256>>>();
    {
        dim3 g(HH/BN, CAPE/BM, EE);               // (16,6,32)
        gemm_routed2<<<g, 256>>>(w2);
    }

    // shared-expert path (writes d_out fully)
    {
        dim3 g((2*ISH)/BN, TT/BM, 1);             // (24,8)
        gemm_shared1<<<g, 256>>>(x, sgu);
    }
    swiglu_shared<<<TT, 256>>>();
    {
        dim3 g(HH/BN, TT/BM, 1);                  // (16,8)
        gemm_shared2<<<g, 256>>>(sdn, out);
    }

    // combine routed into out
    combine_kernel<<<TT, 256>>>(out);
}

// round 8
// speedup vs baseline: 3.1716x; 1.1892x over previous
#include <cuda_runtime.h>
#include <cuda_bf16.h>
#include <math.h>
#include <stdint.h>

// ---------------- problem constants ----------------
#define TT     1024      // tokens
#define HH     2048      // hidden
#define EE     32        // routed experts
#define TOPK   6
#define NGROUP 8
#define TOPKG  3
#define EPG    (EE/NGROUP)   // 4 experts per group
#define IMOE   768
#define ISH    1536          // 2 * IMOE
#define CAPE   768           // per-expert capacity
#define RSCALE 16.0f

// ---------------- scratch (static device globals; no allocation) ----------------
__device__ float g_logits[(size_t)TT*EE];            // router logits [1024,32]
__device__ float g_gu   [(size_t)TT*TOPK * 2*IMOE];  // routed gate_up outputs  [6144,1536]
__device__ float g_h    [(size_t)TT*TOPK * IMOE];    // routed silu*up          [6144, 768]
__device__ float g_y    [(size_t)TT*TOPK * HH];      // routed expert outputs   [6144,2048]
__device__ float g_gu_sh[(size_t)TT * 2*ISH];        // shared gate_up          [1024,3072]
__device__ float g_h_sh [(size_t)TT * ISH];          // shared silu*up          [1024,1536]
__device__ float g_wcomb[TT*TOPK];                   // combine weights (0 if dropped)
__device__ int   g_slot_tok [EE*CAPE];               // token index per expert slot
__device__ int   g_slot_flat[EE*CAPE];               // flat (t*K+k) per expert slot
__device__ int   g_cnt[EE];                          // per-expert assignment count

// ---------------- init ----------------
__global__ void init_kernel() {
    if (threadIdx.x < EE) g_cnt[threadIdx.x] = 0;
}

// ---------------- router logits: one thread per (t,e), SEQUENTIAL ascending-k fp32 fma ----
// Bit-replicates the reference's per-output single-accumulator ascending-k chain.
// DO NOT TOUCH: this exact ordering is what makes routing decisions match.
__global__ void logits_kernel(const float* __restrict__ x,
                              const float* __restrict__ gate_w) {
    __shared__ float sx[4][HH];               // 4 tokens staged, 32KB
    const int t0 = blockIdx.x * 4;
    const int tid = threadIdx.x;              // 128 threads: 4 tokens x 32 experts
    for (int i = tid; i < 4*HH; i += 128)
        sx[i >> 11][i & (HH-1)] = x[(size_t)(t0 + (i >> 11)) * HH + (i & (HH-1))];
    __syncthreads();

    const int tl = tid & 3;
    const int e  = tid >> 2;
    const float* gw = gate_w + (size_t)e * HH;
    float acc = 0.f;
    #pragma unroll 8
    for (int k = 0; k < HH; ++k)
        acc = fmaf(sx[tl][k], gw[k], acc);    // single chain, ascending k
    g_logits[(size_t)(t0 + tl) * EE + e] = acc;
}

// ---------------- selection: fp32 softmax (jax form) + group-limited top-k + dispatch ----
__global__ void select_kernel() {
    const int t = blockIdx.x * blockDim.x + threadIdx.x;
    if (t >= TT) return;
    const float* l = g_logits + (size_t)t * EE;

    float mx = l[0];
    for (int e = 1; e < EE; ++e) mx = fmaxf(mx, l[e]);
    float ex[EE]; float sum = 0.f;
    for (int e = 0; e < EE; ++e) { ex[e] = expf(l[e] - mx); sum += ex[e]; }
    float sc[EE];
    for (int e = 0; e < EE; ++e) sc[e] = ex[e] / sum;

    float gs[NGROUP];
    for (int g = 0; g < NGROUP; ++g) {
        float m = sc[g * EPG];
        for (int j = 1; j < EPG; ++j) m = fmaxf(m, sc[g * EPG + j]);
        gs[g] = m;
    }
    bool gsel[NGROUP];
    for (int g = 0; g < NGROUP; ++g) gsel[g] = false;
    for (int r = 0; r < TOPKG; ++r) {
        int best = -1; float bv = -1e30f;
        for (int g = 0; g < NGROUP; ++g)
            if (!gsel[g] && gs[g] > bv) { bv = gs[g]; best = g; }
        gsel[best] = true;
    }
    float ms[EE];
    for (int e = 0; e < EE; ++e) ms[e] = gsel[e / EPG] ? sc[e] : 0.f;
    for (int k = 0; k < TOPK; ++k) {
        int best = 0; float bv = -1.f;
        for (int e = 0; e < EE; ++e)
            if (ms[e] > bv) { bv = ms[e]; best = e; }
        ms[best] = -1.f;
        const int flat = t * TOPK + k;
        const int pos = atomicAdd(&g_cnt[best], 1);
        if (pos < CAPE) {
            g_slot_tok [best * CAPE + pos] = t;
            g_slot_flat[best * CAPE + pos] = flat;
            g_wcomb[flat] = bv;
        } else {
            g_wcomb[flat] = 0.f;
        }
    }
}

// ================= TF32 tensor-core NT GEMM, cp.async double-buffered =================
// C[m,n] = sum_k A[m,k]*B[n,k]; operands cvt.rna.tf32 at fragment load (cublas
// semantics, bit-identical to round-7 kernel), fp32 acc.
// 128x128x32 block tile, 256 threads = 2x4 warps, warp tile 64x32, mma.m16n8k8.
#define BM 128
#define BN 128
#define BKK 32
#define SPAD 4
#define SROW (BKK + SPAD)          // 36 words; 144B row stride (16B-aligned)
#define STAGE_FLTS (BM * SROW)     // per-matrix per-stage floats (4608)
#define SMEM_FLTS  (4 * STAGE_FLTS) // A0,A1,B0,B1 = 73728B

__device__ __forceinline__ uint32_t tf32b(float x) {
    uint32_t u;
    asm("cvt.rna.tf32.f32 %0, %1;" : "=r"(u) : "f"(x));
    return u;
}

__device__ __forceinline__ void mma_tf32(float c[4], const uint32_t a[4], const uint32_t b[2]) {
    asm volatile(
        "mma.sync.aligned.m16n8k8.row.col.f32.tf32.tf32.f32 "
        "{%0,%1,%2,%3}, {%4,%5,%6,%7}, {%8,%9}, {%0,%1,%2,%3};\n"
        : "+f"(c[0]), "+f"(c[1]), "+f"(c[2]), "+f"(c[3])
        : "r"(a[0]), "r"(a[1]), "r"(a[2]), "r"(a[3]), "r"(b[0]), "r"(b[1]));
}

__device__ __forceinline__ void cp16(uint32_t smem_addr, const float* gptr, int srcsize) {
    asm volatile("cp.async.cg.shared.global [%0], [%1], 16, %2;\n"
                 :: "r"(smem_addr), "l"(gptr), "r"(srcsize));
}

__device__ __forceinline__ void gemm_tc_body(
    const float* __restrict__ A, int lda,
    const float* __restrict__ B,            // row-major [N, Klen]
    float* __restrict__ C, int ldc,
    const int* __restrict__ arow,           // nullable: A row = arow[m]
    const int* __restrict__ crow,           // nullable: C row = crow[m]
    int M, int Klen)
{
    const int m0 = blockIdx.y * BM;
    if (m0 >= M) return;
    const int n0 = blockIdx.x * BN;

    extern __shared__ float smem[];
    float* Asf = smem;                        // [2][BM][SROW]
    float* Bsf = smem + 2 * STAGE_FLTS;       // [2][BN][SROW]
    const uint32_t smem_base = (uint32_t)__cvta_generic_to_shared(smem);
    const uint32_t As_u = smem_base;
    const uint32_t Bs_u = smem_base + 2 * STAGE_FLTS * 4;

    const int tid  = threadIdx.x;
    const int warp = tid >> 5, lane = tid & 31;
    const int wm = (warp & 1) * 64;           // warp m-offset within block
    const int wn = (warp >> 1) * 32;          // warp n-offset within block
    const int gid = lane >> 2, tig = lane & 3;

    // global-load mapping: each thread cp.async's one float4 per pass; 4 passes/matrix
    const int lrow = tid >> 3;                // 0..31
    const int lcol = (tid & 7) * 4;           // 0,4,...,28

    // resolve gathered A rows once
    long long arows[4]; int asz[4];
    #pragma unroll
    for (int p = 0; p < 4; ++p) {
        const int m = m0 + lrow + p * 32;
        const bool ok = m < M;
        asz[p] = ok ? 16 : 0;                 // cp.async src-size 0 => zero-fill
        arows[p] = ok ? (arow ? arow[m] : m) : 0;
    }
    const long long brow = (long long)(n0 + lrow) * Klen;

    float acc[4][4][4];
    #pragma unroll
    for (int i = 0; i < 4; ++i)
        #pragma unroll
        for (int j = 0; j < 4; ++j)
            #pragma unroll
            for (int r = 0; r < 4; ++r) acc[i][j][r] = 0.f;

    // ---- prefetch helper (stage st, k-offset k0) ----
    auto prefetch = [&](int st, int k0) {
        const uint32_t abase = As_u + (uint32_t)(st * STAGE_FLTS) * 4;
        const uint32_t bbase = Bs_u + (uint32_t)(st * STAGE_FLTS) * 4;
        #pragma unroll
        for (int p = 0; p < 4; ++p) {
            const int r = lrow + p * 32;
            cp16(abase + (uint32_t)(r * SROW + lcol) * 4,
                 A + arows[p] * (long long)lda + k0 + lcol, asz[p]);
            cp16(bbase + (uint32_t)(r * SROW + lcol) * 4,
                 B + brow + (long long)p * 32 * Klen + k0 + lcol, 16);
        }
        asm volatile("cp.async.commit_group;\n");
    };

    prefetch(0, 0);

    int s = 0;
    for (int k0 = 0; k0 < Klen; k0 += BKK, s ^= 1) {
        const bool has_next = (k0 + BKK) < Klen;
        if (has_next) prefetch(s ^ 1, k0 + BKK);
        if (has_next) asm volatile("cp.async.wait_group 1;\n");
        else          asm volatile("cp.async.wait_group 0;\n");
        __syncthreads();

        const float* As = Asf + s * STAGE_FLTS;
        const float* Bs = Bsf + s * STAGE_FLTS;
        #pragma unroll
        for (int kk = 0; kk < BKK; kk += 8) {
            uint32_t af[4][4], bf[4][2];
            #pragma unroll
            for (int mt = 0; mt < 4; ++mt) {
                const int r = wm + mt * 16 + gid;
                af[mt][0] = tf32b(As[ r      * SROW + kk + tig    ]);
                af[mt][1] = tf32b(As[(r + 8) * SROW + kk + tig    ]);
                af[mt][2] = tf32b(As[ r      * SROW + kk + tig + 4]);
                af[mt][3] = tf32b(As[(r + 8) * SROW + kk + tig + 4]);
            }
            #pragma unroll
            for (int nt = 0; nt < 4; ++nt) {
                const int r = wn + nt * 8 + gid;
                bf[nt][0] = tf32b(Bs[r * SROW + kk + tig    ]);
                bf[nt][1] = tf32b(Bs[r * SROW + kk + tig + 4]);
            }
            #pragma unroll
            for (int mt = 0; mt < 4; ++mt)
                #pragma unroll
                for (int nt = 0; nt < 4; ++nt)
                    mma_tf32(acc[mt][nt], af[mt], bf[nt]);
        }
        __syncthreads();
    }

    // epilogue: c0,c1 at (gid, 2*tig), c2,c3 at (gid+8, 2*tig)
    #pragma unroll
    for (int mt = 0; mt < 4; ++mt) {
        const int ma = m0 + wm + mt * 16 + gid;
        const int mb = ma + 8;
        #pragma unroll
        for (int nt = 0; nt < 4; ++nt) {
            const int col = n0 + wn + nt * 8 + 2 * tig;
            if (ma < M) {
                const long long r = crow ? crow[ma] : ma;
                *(float2*)(C + r * (long long)ldc + col) = make_float2(acc[mt][nt][0], acc[mt][nt][1]);
            }
            if (mb < M) {
                const long long r = crow ? crow[mb] : mb;
                *(float2*)(C + r * (long long)ldc + col) = make_float2(acc[mt][nt][2], acc[mt][nt][3]);
            }
        }
    }
}

// ---- GEMM wrappers (blockIdx.z = expert where applicable) ----
__global__ void __launch_bounds__(256, 2) gemm_routed1(const float* __restrict__ x, const float* __restrict__ w13) {
    const int e = blockIdx.z;
    const int M = min(g_cnt[e], CAPE);
    gemm_tc_body(x, HH,
                 w13 + (long long)e * (2*IMOE) * HH,
                 g_gu, 2*IMOE,
                 g_slot_tok + e*CAPE, g_slot_flat + e*CAPE,
                 M, HH);
}
__global__ void __launch_bounds__(256, 2) gemm_routed2(const float* __restrict__ w2) {
    const int e = blockIdx.z;
    const int M = min(g_cnt[e], CAPE);
    gemm_tc_body(g_h, IMOE,
                 w2 + (long long)e * HH * IMOE,
                 g_y, HH,
                 g_slot_flat + e*CAPE, g_slot_flat + e*CAPE,
                 M, IMOE);
}
__global__ void __launch_bounds__(256, 2) gemm_shared1(const float* __restrict__ x, const float* __restrict__ sgu) {
    gemm_tc_body(x, HH, sgu, g_gu_sh, 2*ISH, nullptr, nullptr, TT, HH);
}
__global__ void __launch_bounds__(256, 2) gemm_shared2(const float* __restrict__ sdn, float* __restrict__ out) {
    gemm_tc_body(g_h_sh, ISH, sdn, out, HH, nullptr, nullptr, TT, ISH);
}

// ---------------- SwiGLU elementwise (exact fp32) ----------------
__global__ void swiglu_routed() {
    const int slot = blockIdx.x;                 // e*CAPE + pos
    const int e = slot / CAPE, pos = slot % CAPE;
    if (pos >= g_cnt[e]) return;
    const int flat = g_slot_flat[slot];
    const float* gu = g_gu + (long long)flat * (2*IMOE);
    float* h = g_h + (long long)flat * IMOE;
    for (int i = threadIdx.x; i < IMOE; i += blockDim.x) {
        float g = gu[i], u = gu[i + IMOE];
        h[i] = u * g / (1.f + expf(-g));
    }
}
__global__ void swiglu_shared() {
    const int t = blockIdx.x;
    const float* gu = g_gu_sh + (long long)t * (2*ISH);
    float* h = g_h_sh + (long long)t * ISH;
    for (int i = threadIdx.x; i < ISH; i += blockDim.x) {
        float g = gu[i], u = gu[i + ISH];
        h[i] = u * g / (1.f + expf(-g));
    }
}

// ---------------- combine: out += SCALE * sum_k w_k * y_k ----------------
__global__ void combine_kernel(float* __restrict__ out) {
    const int t = blockIdx.x;
    const int base = t * TOPK;
    float w[TOPK];
    #pragma unroll
    for (int k = 0; k < TOPK; ++k) w[k] = g_wcomb[base + k];
    float* orow = out + (long long)t * HH;
    for (int h = threadIdx.x; h < HH; h += blockDim.x) {
        float r = 0.f;
        #pragma unroll
        for (int k = 0; k < TOPK; ++k)
            r += w[k] * g_y[(long long)(base + k) * HH + h];
        orow[h] += RSCALE * r;
    }
}

// ---------------- launch ----------------
extern "C" void kernel_launch(void* const* d_in, const int* in_sizes, int n_in,
                              void* d_out, int out_size) {
    const float* x     = (const float*)d_in[0];   // [T,H]
    const float* gatew = (const float*)d_in[1];   // [E,H]
    const float* w13   = (const float*)d_in[2];   // [E,2I,H]
    const float* w2    = (const float*)d_in[3];   // [E,H,I]
    const float* sgu   = (const float*)d_in[4];   // [2*ISH,H]
    const float* sdn   = (const float*)d_in[5];   // [H,ISH]
    float* out = (float*)d_out;                   // [T,H]

    const int smem_bytes = SMEM_FLTS * 4;         // 73728
    static bool attr_set = false;
    if (!attr_set) {
        cudaFuncSetAttribute(gemm_routed1, cudaFuncAttributeMaxDynamicSharedMemorySize, smem_bytes);
        cudaFuncSetAttribute(gemm_routed2, cudaFuncAttributeMaxDynamicSharedMemorySize, smem_bytes);
        cudaFuncSetAttribute(gemm_shared1, cudaFuncAttributeMaxDynamicSharedMemorySize, smem_bytes);
        cudaFuncSetAttribute(gemm_shared2, cudaFuncAttributeMaxDynamicSharedMemorySize, smem_bytes);
        attr_set = true;
    }

    init_kernel<<<1, 32>>>();
    logits_kernel<<<TT/4, 128>>>(x, gatew);
    select_kernel<<<4, 256>>>();

    // routed path
    {
        dim3 g((2*IMOE)/BN, CAPE/BM, EE);         // (12,6,32)
        gemm_routed1<<<g, 256, smem_bytes>>>(x, w13);
    }
    swiglu_routed<<<EE*CAPE, 256>>>();
    {
        dim3 g(HH/BN, CAPE/BM, EE);               // (16,6,32)
        gemm_routed2<<<g, 256, smem_bytes>>>(w2);
    }

    // shared-expert path (writes d_out fully)
    {
        dim3 g((2*ISH)/BN, TT/BM, 1);             // (24,8)
        gemm_shared1<<<g, 256, smem_bytes>>>(x, sgu);
    }
    swiglu_shared<<<TT, 256>>>();
    {
        dim3 g(HH/BN, TT/BM, 1);                  // (16,8)
        gemm_shared2<<<g, 256, smem_bytes>>>(sdn, out);
    }

    // combine routed into out
    combine_kernel<<<TT, 256>>>(out);
}